// round 15
// baseline (speedup 1.0000x reference)
#include <cuda_runtime.h>
#include <cuda_bf16.h>
#include <cuda_fp16.h>
#include <math.h>
#include <stdint.h>

#define B_    16
#define S_    577
#define D_    1280
#define H_    16
#define HD_   80
#define HALF_ 40
#define M_    (B_*S_)   // 9232
#define K_    1280
#define N_    1280

// ---------------------------------------------------------------- scratch
__device__ __align__(16) __half g_hs16[M_*K_];
__device__ __align__(16) __half g_w16[4*K_*N_];
__device__ __align__(16) __half g_at16[M_*K_];
__device__ __align__(16) __half g_q16[B_*H_*S_*HD_];
__device__ __align__(16) __half g_k16[B_*H_*S_*HD_];
__device__ __align__(16) __half g_v16[B_*H_*S_*HD_];

// ---------------------------------------------------------------- helpers
__device__ __forceinline__ uint32_t smem_u32(const void* p) {
    uint32_t a;
    asm("{ .reg .u64 t; cvta.to.shared.u64 t, %1; cvt.u32.u64 %0, t; }"
        : "=r"(a) : "l"(p));
    return a;
}
__device__ __forceinline__ void cp16(uint32_t dst, const void* src, int sz) {
    asm volatile("cp.async.cg.shared.global [%0], [%1], 16, %2;"
                 :: "r"(dst), "l"(src), "r"(sz) : "memory");
}
#define CP_COMMIT() asm volatile("cp.async.commit_group;" ::: "memory")
#define CP_WAIT0()  asm volatile("cp.async.wait_group 0;" ::: "memory")
#define CP_WAIT1()  asm volatile("cp.async.wait_group 1;" ::: "memory")

__device__ __forceinline__ void ldx4(uint32_t* r, uint32_t addr) {
    asm volatile("ldmatrix.sync.aligned.m8n8.x4.shared.b16 {%0,%1,%2,%3}, [%4];"
                 : "=r"(r[0]), "=r"(r[1]), "=r"(r[2]), "=r"(r[3]) : "r"(addr));
}
__device__ __forceinline__ void ldx4t(uint32_t* r, uint32_t addr) {
    asm volatile("ldmatrix.sync.aligned.m8n8.x4.trans.shared.b16 {%0,%1,%2,%3}, [%4];"
                 : "=r"(r[0]), "=r"(r[1]), "=r"(r[2]), "=r"(r[3]) : "r"(addr));
}
__device__ __forceinline__ void hmma16(float* d, const uint32_t* a, const uint32_t* b) {
    asm volatile(
        "mma.sync.aligned.m16n8k16.row.col.f32.f16.f16.f32 "
        "{%0,%1,%2,%3}, {%4,%5,%6,%7}, {%8,%9}, {%0,%1,%2,%3};"
        : "+f"(d[0]), "+f"(d[1]), "+f"(d[2]), "+f"(d[3])
        : "r"(a[0]), "r"(a[1]), "r"(a[2]), "r"(a[3]), "r"(b[0]), "r"(b[1]));
}

// ---------------------------------------------------------------- merged fp32 -> fp16 converts
__global__ __launch_bounds__(256)
void conv_all(const float* __restrict__ hs,
              const float* __restrict__ w0, const float* __restrict__ w1,
              const float* __restrict__ w2, const float* __restrict__ w3,
              __half* __restrict__ hs16, __half* __restrict__ w16)
{
    const int n1 = M_ * K_;
    const int nw = K_ * N_;
    int i = blockIdx.x * blockDim.x + threadIdx.x;
    if (i < n1) {
        hs16[i] = __float2half_rn(hs[i]);
    } else {
        int k = i - n1;
        if (k >= 4 * nw) return;
        int mat = k / nw, off = k - mat * nw;
        const float* src = (mat == 0) ? w0 : (mat == 1) ? w1 : (mat == 2) ? w2 : w3;
        w16[k] = __float2half_rn(src[off]);
    }
}

// ---------------------------------------------------------------- fp16 HMMA GEMM
// CTA tile 128x128, BK=32; 8 warps as 2(M) x 4(N), warp tile 64x32.
// Fragment double-buffered: both kk halves' ldmatrix issued before HMMAs,
// letting ptxas overlap kk=1 LDSM under kk=0 HMMA burst.
#define SPADB 80
#define TILEB (128*SPADB)
#define STAGEB (2*TILEB)
#define GEMM_SMEM (3*STAGEB)
#define NIT (K_/32)

template<int MODE>
__global__ __launch_bounds__(256, 2)
void gemm_hmma(const __half* __restrict__ Ah, const __half* __restrict__ Bh,
               const float* __restrict__ bq, const float* __restrict__ bk,
               const float* __restrict__ bv,
               float* __restrict__ Cf,
               __half* __restrict__ q16, __half* __restrict__ k16,
               __half* __restrict__ v16,
               const float* __restrict__ fc, const float* __restrict__ fs,
               int M)
{
    extern __shared__ __align__(16) char smem[];
    const int tid = threadIdx.x, wid = tid >> 5, lane = tid & 31;
    const int bn = blockIdx.x, bm = blockIdx.y;
    const int wm = wid >> 2, wn = wid & 3;
    const int row0A = bm * 128, row0B = bn * 128;
    const uint32_t sbase = smem_u32(smem);

    float acc[4][4][4];
#pragma unroll
    for (int i = 0; i < 4; i++)
#pragma unroll
        for (int j = 0; j < 4; j++)
#pragma unroll
            for (int c = 0; c < 4; c++) acc[i][j][c] = 0.f;

    auto load_stage = [&](int st, int k0) {
        uint32_t sdst = sbase + st * STAGEB;
#pragma unroll
        for (int t = 0; t < 4; t++) {
            int idx = tid + t * 256;
            int tile = idx >> 9;
            int w = idx & 511;
            int r = w >> 2, seg = w & 3;
            uint32_t d = sdst + tile * TILEB + r * SPADB + seg * 16;
            const __half* sp;
            int sz = 16;
            if (tile == 0) {
                int row = row0A + r;
                if (row >= M) { row = M - 1; sz = 0; }
                sp = Ah + (size_t)row * K_ + k0 + seg * 8;
            } else {
                int row = row0B + r;
                sp = Bh + (size_t)row * K_ + k0 + seg * 8;
            }
            cp16(d, sp, sz);
        }
        CP_COMMIT();
    };

    const uint32_t a_lane = (uint32_t)((wm * 64 + (lane & 15)) * SPADB + (lane >> 4) * 16);
    const uint32_t b_lane = (uint32_t)((wn * 32 + ((lane >> 4) << 3) + (lane & 7)) * SPADB
                                       + ((lane >> 3) & 1) * 16);

    load_stage(0, 0);
    load_stage(1, 32);

    for (int it = 0; it < NIT; it++) {
        int cur = it % 3;
        if (it + 2 < NIT) load_stage((it + 2) % 3, (it + 2) * 32);
        if (it + 2 < NIT)      { asm volatile("cp.async.wait_group 2;" ::: "memory"); }
        else if (it + 1 < NIT) { CP_WAIT1(); }
        else                   { CP_WAIT0(); }
        __syncthreads();

        uint32_t scur = sbase + cur * STAGEB;
        const uint32_t ab = scur + a_lane;
        const uint32_t bb = scur + TILEB + b_lane;

        // fragment double-buffer: all 16 ldx4 before the HMMA bursts
        uint32_t af0[4][4], bf0[4][2], af1[4][4], bf1[4][2];
#pragma unroll
        for (int mi = 0; mi < 4; mi++) ldx4(af0[mi], ab + mi * 16 * SPADB);
#pragma unroll
        for (int np = 0; np < 2; np++) {
            uint32_t r[4];
            ldx4(r, bb + np * 16 * SPADB);
            bf0[np * 2][0] = r[0]; bf0[np * 2][1] = r[1];
            bf0[np * 2 + 1][0] = r[2]; bf0[np * 2 + 1][1] = r[3];
        }
#pragma unroll
        for (int mi = 0; mi < 4; mi++) ldx4(af1[mi], ab + 32 + mi * 16 * SPADB);
#pragma unroll
        for (int np = 0; np < 2; np++) {
            uint32_t r[4];
            ldx4(r, bb + 32 + np * 16 * SPADB);
            bf1[np * 2][0] = r[0]; bf1[np * 2][1] = r[1];
            bf1[np * 2 + 1][0] = r[2]; bf1[np * 2 + 1][1] = r[3];
        }
#pragma unroll
        for (int mi = 0; mi < 4; mi++)
#pragma unroll
            for (int ni = 0; ni < 4; ni++) hmma16(acc[mi][ni], af0[mi], bf0[ni]);
#pragma unroll
        for (int mi = 0; mi < 4; mi++)
#pragma unroll
            for (int ni = 0; ni < 4; ni++) hmma16(acc[mi][ni], af1[mi], bf1[ni]);

        __syncthreads();
    }

    // ---- epilogue ----
    const int mrow = (lane >> 2);
    const int ncol = (lane & 3) * 2;
    const float rscale = 0.11180339887498949f;  // 1/sqrt(80)

    int mat = 0;
    const float* bias = bq;
    if (MODE == 1) {
        mat = bn / 10;
        bias = (mat == 0) ? bq : (mat == 1) ? bk : bv;
    }
    const int nbase = (MODE == 1) ? (bn % 10) * 128 : bn * 128;

#pragma unroll
    for (int mi = 0; mi < 4; mi++) {
#pragma unroll
        for (int h2 = 0; h2 < 2; h2++) {
            int m = row0A + wm * 64 + mi * 16 + mrow + h2 * 8;
            if (m >= M) continue;
            int bb2 = m / S_, ss = m - bb2 * S_;
#pragma unroll
            for (int ni = 0; ni < 4; ni++) {
                int n0 = nbase + wn * 32 + ni * 8 + ncol;
                float vx = acc[mi][ni][h2 * 2] + bias[n0];
                float vy = acc[mi][ni][h2 * 2 + 1] + bias[n0 + 1];
                if (MODE == 0) {
                    float2 v = make_float2(vx, vy);
                    *(float2*)&Cf[(size_t)m * N_ + n0] = v;
                } else {
                    int h = n0 / HD_, d = n0 - h * HD_;
                    size_t idx = ((size_t)(bb2 * H_ + h) * S_ + ss) * HD_ + d;
                    if (mat == 0) {            // q: rope + scale
                        int j = d >> 1;
                        float c = fc[ss * HALF_ + j], sn = fs[ss * HALF_ + j];
                        float rx = (vx * c - vy * sn) * rscale;
                        float ry = (vx * sn + vy * c) * rscale;
                        __half2 hv = __floats2half2_rn(rx, ry);
                        *(__half2*)&q16[idx] = hv;
                    } else if (mat == 1) {     // k: rope
                        int j = d >> 1;
                        float c = fc[ss * HALF_ + j], sn = fs[ss * HALF_ + j];
                        float rx = vx * c - vy * sn;
                        float ry = vx * sn + vy * c;
                        __half2 hv = __floats2half2_rn(rx, ry);
                        *(__half2*)&k16[idx] = hv;
                    } else {                   // v
                        __half2 hv = __floats2half2_rn(vx, vy);
                        *(__half2*)&v16[idx] = hv;
                    }
                }
            }
        }
    }
}

// ---------------------------------------------------------------- fp16 HMMA flash attention (R14)
#define ASVB 176                  // 80 fp16 = 160B + 16B pad (col80=1.0, 81..87=0)
#define AQ_TILE (128*ASVB)        // 22528
#define AKV_TILE (64*ASVB)        // 11264
#define ATT_SMEM (AQ_TILE + 4*AKV_TILE)   // 67584

__global__ __launch_bounds__(256, 2)
void attn_hmma(const __half* __restrict__ q16,
               const __half* __restrict__ k16, const __half* __restrict__ v16,
               __half* __restrict__ at16)
{
    extern __shared__ __align__(16) char smem[];
    const uint32_t sb = smem_u32(smem);
    const uint32_t kv0 = sb + AQ_TILE;

    const int tid = threadIdx.x, wid = tid >> 5, lane = tid & 31;
    const int qt = blockIdx.x, h = blockIdx.y, b = blockIdx.z;
    const int bh = b * H_ + h;
    const size_t off = (size_t)bh * S_ * HD_;
    const int q0 = qt * 128;

#pragma unroll
    for (int t = 0; t < 5; t++) {
        int i = tid + t * 256;
        int rr = i / 10, seg = i % 10;
        int row = q0 + rr;
        int sz = (row < S_) ? 16 : 0;
        if (row >= S_) row = S_ - 1;
        const __half* sp = q16 + off + (size_t)row * HD_ + seg * 8;
        cp16(sb + rr * ASVB + seg * 16, sp, sz);
    }
    CP_COMMIT();

    auto load_kv = [&](int stage, int kt) {
#pragma unroll
        for (int t = 0; t < 5; t++) {
            int i = tid + t * 256;
            int tile = i / 640;
            int rr = (i % 640) / 10, seg = i % 10;
            int row = kt * 64 + rr;
            int sz = (row < S_) ? 16 : 0;
            if (row >= S_) row = S_ - 1;
            const __half* sp = (tile ? v16 : k16) + off + (size_t)row * HD_ + seg * 8;
            cp16(kv0 + (stage * 2 + tile) * AKV_TILE + rr * ASVB + seg * 16, sp, sz);
        }
        CP_COMMIT();
    };
    load_kv(0, 0);
    load_kv(1, 1);

    // V pad init: col 80 = 1.0 (ones column for row-sum), 81..87 = 0.
    if (tid < 128) {
        int stage = tid >> 6, row = tid & 63;
        __half* p = (__half*)(smem + AQ_TILE + (stage * 2 + 1) * AKV_TILE
                              + row * ASVB + 160);
        p[0] = __float2half(1.f);
#pragma unroll
        for (int z = 1; z < 8; z++) p[z] = __float2half(0.f);
    }

    CP_WAIT1();
    __syncthreads();

    const int r0 = lane >> 2, c0 = (lane & 3) * 2;
    float mreg[2] = {-1e30f, -1e30f};
    float out[11][4];
#pragma unroll
    for (int ni = 0; ni < 11; ni++)
#pragma unroll
        for (int c = 0; c < 4; c++) out[ni][c] = 0.f;

    for (int kt = 0; kt < 10; kt++) {
        const int cur = kt & 1;
        const uint32_t kbase = kv0 + cur * 2 * AKV_TILE;
        const uint32_t vbase0 = kbase + AKV_TILE;

        float sacc[8][4];
#pragma unroll
        for (int ni = 0; ni < 8; ni++)
#pragma unroll
            for (int c = 0; c < 4; c++) sacc[ni][c] = 0.f;

#pragma unroll
        for (int k16i = 0; k16i < 5; k16i++) {
            uint32_t qf[4], bf[8][2];
            uint32_t abase = sb + (wid * 16 + (lane & 15)) * ASVB
                           + (lane >> 4) * 16 + k16i * 32;
            ldx4(qf, abase);
#pragma unroll
            for (int nt = 0; nt < 4; nt++) {
                uint32_t r[4];
                uint32_t bb = kbase + (nt * 16 + ((lane >> 4) << 3) + (lane & 7)) * ASVB
                            + ((lane >> 3) & 1) * 16 + k16i * 32;
                ldx4(r, bb);
                bf[nt * 2][0] = r[0]; bf[nt * 2][1] = r[1];
                bf[nt * 2 + 1][0] = r[2]; bf[nt * 2 + 1][1] = r[3];
            }
#pragma unroll
            for (int ni = 0; ni < 8; ni++) hmma16(sacc[ni], qf, bf[ni]);
        }

        float mloc[2] = {-1e30f, -1e30f};
#pragma unroll
        for (int ni = 0; ni < 8; ni++)
#pragma unroll
            for (int h8 = 0; h8 < 2; h8++)
#pragma unroll
                for (int j = 0; j < 2; j++) {
                    int key = kt * 64 + ni * 8 + c0 + j;
                    float sv = (key < S_) ? sacc[ni][h8 * 2 + j] : -1e30f;
                    sacc[ni][h8 * 2 + j] = sv;
                    mloc[h8] = fmaxf(mloc[h8], sv);
                }
        float alpha[2];
#pragma unroll
        for (int h8 = 0; h8 < 2; h8++) {
            mloc[h8] = fmaxf(mloc[h8], __shfl_xor_sync(0xffffffffu, mloc[h8], 1));
            mloc[h8] = fmaxf(mloc[h8], __shfl_xor_sync(0xffffffffu, mloc[h8], 2));
            float mn = fmaxf(mloc[h8], mreg[h8]);
            alpha[h8] = __expf(mreg[h8] - mn);
            mreg[h8] = mn;
        }

        uint32_t pacc[8][2];
#pragma unroll
        for (int ni = 0; ni < 8; ni++)
#pragma unroll
            for (int h8 = 0; h8 < 2; h8++) {
                float e0 = __expf(sacc[ni][h8 * 2]     - mreg[h8]);
                float e1 = __expf(sacc[ni][h8 * 2 + 1] - mreg[h8]);
                __half2 th = __floats2half2_rn(e0, e1);
                pacc[ni][h8] = *(uint32_t*)&th;
            }

#pragma unroll
        for (int ni = 0; ni < 11; ni++)
#pragma unroll
            for (int h8 = 0; h8 < 2; h8++) {
                out[ni][h8 * 2]     *= alpha[h8];
                out[ni][h8 * 2 + 1] *= alpha[h8];
            }

#pragma unroll
        for (int kk = 0; kk < 4; kk++) {
            uint32_t pa[4] = { pacc[kk * 2][0], pacc[kk * 2][1],
                               pacc[kk * 2 + 1][0], pacc[kk * 2 + 1][1] };
            uint32_t vb = vbase0 + (kk * 16 + (lane & 15)) * ASVB + (lane >> 4) * 16;
#pragma unroll
            for (int nt = 0; nt < 5; nt++) {
                uint32_t rh[4];
                ldx4t(rh, vb + nt * 32);
                uint32_t vb0[2] = {rh[0], rh[1]}, vb1[2] = {rh[2], rh[3]};
                hmma16(out[nt * 2], pa, vb0);
                hmma16(out[nt * 2 + 1], pa, vb1);
            }
            {
                uint32_t rh[4];
                uint32_t vbo = vbase0 + (kk * 16 + (lane & 15)) * ASVB + 160;
                ldx4t(rh, vbo);
                uint32_t vb0[2] = {rh[0], rh[1]};
                hmma16(out[10], pa, vb0);
            }
        }

        __syncthreads();
        if (kt + 2 < 10) {
            load_kv(cur, kt + 2);
            CP_WAIT1();
        } else if (kt + 1 < 10) {
            CP_WAIT0();
        }
    }

#pragma unroll
    for (int h8 = 0; h8 < 2; h8++) {
        float l = __shfl_sync(0xffffffffu, out[10][h8 * 2], lane & ~3);
        int row = wid * 16 + r0 + h8 * 8;
        int srow = q0 + row;
        if (srow >= S_) continue;
        float rl = 1.f / l;
#pragma unroll
        for (int ni = 0; ni < 10; ni++) {
            int col = ni * 8 + c0;
            float vx = out[ni][h8 * 2] * rl;
            float vy = out[ni][h8 * 2 + 1] * rl;
            __half2 hv = __floats2half2_rn(vx, vy);
            size_t oidx = ((size_t)b * S_ + srow) * D_ + h * HD_ + col;
            *(__half2*)&at16[oidx] = hv;
        }
    }
}

// ----------------------------------------------------------------
extern "C" void kernel_launch(void* const* d_in, const int* in_sizes, int n_in,
                              void* d_out, int out_size)
{
    const float* hs = (const float*)d_in[0];
    const float* fc = (const float*)d_in[1];
    const float* fs = (const float*)d_in[2];
    const float* Wq = (const float*)d_in[3];
    const float* bq = (const float*)d_in[4];
    const float* Wk = (const float*)d_in[5];
    const float* bk = (const float*)d_in[6];
    const float* Wv = (const float*)d_in[7];
    const float* bv = (const float*)d_in[8];
    const float* Wo = (const float*)d_in[9];
    const float* bo = (const float*)d_in[10];
    float* out = (float*)d_out;

    __half *hs16, *w16, *at16, *q16, *k16, *v16;
    cudaGetSymbolAddress((void**)&hs16, g_hs16);
    cudaGetSymbolAddress((void**)&w16, g_w16);
    cudaGetSymbolAddress((void**)&at16, g_at16);
    cudaGetSymbolAddress((void**)&q16, g_q16);
    cudaGetSymbolAddress((void**)&k16, g_k16);
    cudaGetSymbolAddress((void**)&v16, g_v16);

    {
        int ntot = M_ * K_ + 4 * K_ * N_;
        conv_all<<<(ntot + 255) / 256, 256>>>(hs, Wq, Wk, Wv, Wo, hs16, w16);
    }

    cudaFuncSetAttribute(gemm_hmma<0>, cudaFuncAttributeMaxDynamicSharedMemorySize,
                         GEMM_SMEM);
    cudaFuncSetAttribute(gemm_hmma<1>, cudaFuncAttributeMaxDynamicSharedMemorySize,
                         GEMM_SMEM);
    size_t wsz = (size_t)K_ * N_;

    gemm_hmma<1><<<dim3(30, (M_ + 127) / 128), 256, GEMM_SMEM>>>(
        hs16, w16, bq, bk, bv,
        nullptr, q16, k16, v16, fc, fs, M_);

    cudaFuncSetAttribute(attn_hmma, cudaFuncAttributeMaxDynamicSharedMemorySize,
                         ATT_SMEM);
    attn_hmma<<<dim3(5, H_, B_), 256, ATT_SMEM>>>(q16, k16, v16, at16);

    gemm_hmma<0><<<dim3(10, (M_ + 127) / 128), 256, GEMM_SMEM>>>(
        at16, w16 + 3 * wsz, bo, bo, bo,
        out, nullptr, nullptr, nullptr, fc, fs, M_);
}

// round 16
// speedup vs baseline: 1.1052x; 1.1052x over previous
#include <cuda_runtime.h>
#include <cuda_bf16.h>
#include <cuda_fp16.h>
#include <math.h>
#include <stdint.h>

#define B_    16
#define S_    577
#define D_    1280
#define H_    16
#define HD_   80
#define HALF_ 40
#define M_    (B_*S_)   // 9232
#define K_    1280
#define N_    1280

// ---------------------------------------------------------------- scratch
__device__ __align__(16) __half g_hs16[M_*K_];
__device__ __align__(16) __half g_w16[4*K_*N_];
__device__ __align__(16) __half g_at16[M_*K_];
__device__ __align__(16) __half g_q16[B_*H_*S_*HD_];
__device__ __align__(16) __half g_k16[B_*H_*S_*HD_];
__device__ __align__(16) __half g_v16[B_*H_*S_*HD_];

// ---------------------------------------------------------------- helpers
__device__ __forceinline__ uint32_t smem_u32(const void* p) {
    uint32_t a;
    asm("{ .reg .u64 t; cvta.to.shared.u64 t, %1; cvt.u32.u64 %0, t; }"
        : "=r"(a) : "l"(p));
    return a;
}
__device__ __forceinline__ void cp16(uint32_t dst, const void* src, int sz) {
    asm volatile("cp.async.cg.shared.global [%0], [%1], 16, %2;"
                 :: "r"(dst), "l"(src), "r"(sz) : "memory");
}
#define CP_COMMIT() asm volatile("cp.async.commit_group;" ::: "memory")
#define CP_WAIT0()  asm volatile("cp.async.wait_group 0;" ::: "memory")
#define CP_WAIT1()  asm volatile("cp.async.wait_group 1;" ::: "memory")
#define CP_WAIT2()  asm volatile("cp.async.wait_group 2;" ::: "memory")

__device__ __forceinline__ void ldx4(uint32_t* r, uint32_t addr) {
    asm volatile("ldmatrix.sync.aligned.m8n8.x4.shared.b16 {%0,%1,%2,%3}, [%4];"
                 : "=r"(r[0]), "=r"(r[1]), "=r"(r[2]), "=r"(r[3]) : "r"(addr));
}
__device__ __forceinline__ void ldx4t(uint32_t* r, uint32_t addr) {
    asm volatile("ldmatrix.sync.aligned.m8n8.x4.trans.shared.b16 {%0,%1,%2,%3}, [%4];"
                 : "=r"(r[0]), "=r"(r[1]), "=r"(r[2]), "=r"(r[3]) : "r"(addr));
}
__device__ __forceinline__ void hmma16(float* d, const uint32_t* a, const uint32_t* b) {
    asm volatile(
        "mma.sync.aligned.m16n8k16.row.col.f32.f16.f16.f32 "
        "{%0,%1,%2,%3}, {%4,%5,%6,%7}, {%8,%9}, {%0,%1,%2,%3};"
        : "+f"(d[0]), "+f"(d[1]), "+f"(d[2]), "+f"(d[3])
        : "r"(a[0]), "r"(a[1]), "r"(a[2]), "r"(a[3]), "r"(b[0]), "r"(b[1]));
}

// ---------------------------------------------------------------- merged fp32 -> fp16 converts
__global__ __launch_bounds__(256)
void conv_all(const float* __restrict__ hs,
              const float* __restrict__ w0, const float* __restrict__ w1,
              const float* __restrict__ w2, const float* __restrict__ w3,
              __half* __restrict__ hs16, __half* __restrict__ w16)
{
    const int n1 = M_ * K_;
    const int nw = K_ * N_;
    int i = blockIdx.x * blockDim.x + threadIdx.x;
    if (i < n1) {
        hs16[i] = __float2half_rn(hs[i]);
    } else {
        int k = i - n1;
        if (k >= 4 * nw) return;
        int mat = k / nw, off = k - mat * nw;
        const float* src = (mat == 0) ? w0 : (mat == 1) ? w1 : (mat == 2) ? w2 : w3;
        w16[k] = __float2half_rn(src[off]);
    }
}

// ---------------------------------------------------------------- fp16 HMMA GEMM
// CTA tile 128x128, BK=32; 8 warps as 2(M) x 4(N), warp tile 64x32.
// 4-stage cp.async pipeline, ONE __syncthreads per k-iteration:
// in iter `it` (between sync(it) and sync(it+1)) writes hit buffer (it+2)%4,
// reads hit buffer it%4 -- distance 2 mod 4, never aliased.
#define SPADB 80
#define TILEB (128*SPADB)
#define STAGEB (2*TILEB)
#define GEMM_SMEM (4*STAGEB)      // 81920
#define NIT (K_/32)

template<int MODE>
__global__ __launch_bounds__(256, 2)
void gemm_hmma(const __half* __restrict__ Ah, const __half* __restrict__ Bh,
               const float* __restrict__ bq, const float* __restrict__ bk,
               const float* __restrict__ bv,
               float* __restrict__ Cf,
               __half* __restrict__ q16, __half* __restrict__ k16,
               __half* __restrict__ v16,
               const float* __restrict__ fc, const float* __restrict__ fs,
               int M)
{
    extern __shared__ __align__(16) char smem[];
    const int tid = threadIdx.x, wid = tid >> 5, lane = tid & 31;
    const int bn = blockIdx.x, bm = blockIdx.y;
    const int wm = wid >> 2, wn = wid & 3;
    const int row0A = bm * 128, row0B = bn * 128;
    const uint32_t sbase = smem_u32(smem);

    float acc[4][4][4];
#pragma unroll
    for (int i = 0; i < 4; i++)
#pragma unroll
        for (int j = 0; j < 4; j++)
#pragma unroll
            for (int c = 0; c < 4; c++) acc[i][j][c] = 0.f;

    auto load_stage = [&](int st, int k0) {
        uint32_t sdst = sbase + st * STAGEB;
#pragma unroll
        for (int t = 0; t < 4; t++) {
            int idx = tid + t * 256;
            int tile = idx >> 9;
            int w = idx & 511;
            int r = w >> 2, seg = w & 3;
            uint32_t d = sdst + tile * TILEB + r * SPADB + seg * 16;
            const __half* sp;
            int sz = 16;
            if (tile == 0) {
                int row = row0A + r;
                if (row >= M) { row = M - 1; sz = 0; }
                sp = Ah + (size_t)row * K_ + k0 + seg * 8;
            } else {
                int row = row0B + r;
                sp = Bh + (size_t)row * K_ + k0 + seg * 8;
            }
            cp16(d, sp, sz);
        }
        CP_COMMIT();
    };

    const uint32_t a_lane = (uint32_t)((wm * 64 + (lane & 15)) * SPADB + (lane >> 4) * 16);
    const uint32_t b_lane = (uint32_t)((wn * 32 + ((lane >> 4) << 3) + (lane & 7)) * SPADB
                                       + ((lane >> 3) & 1) * 16);

    load_stage(0, 0);
    load_stage(1, 32);

    for (int it = 0; it < NIT; it++) {
        int cur = it & 3;
        if (it + 2 < NIT) load_stage((it + 2) & 3, (it + 2) * 32);
        if (it + 2 < NIT)      { CP_WAIT2(); }
        else if (it + 1 < NIT) { CP_WAIT1(); }
        else                   { CP_WAIT0(); }
        __syncthreads();   // single barrier per iteration

        uint32_t scur = sbase + cur * STAGEB;
#pragma unroll
        for (int kk = 0; kk < 2; kk++) {
            uint32_t ab = scur + a_lane + kk * 32;
            uint32_t bb = scur + TILEB + b_lane + kk * 32;

            uint32_t af[4][4], bf[4][2];
#pragma unroll
            for (int mi = 0; mi < 4; mi++) ldx4(af[mi], ab + mi * 16 * SPADB);
#pragma unroll
            for (int np = 0; np < 2; np++) {
                uint32_t r[4];
                ldx4(r, bb + np * 16 * SPADB);
                bf[np * 2][0] = r[0]; bf[np * 2][1] = r[1];
                bf[np * 2 + 1][0] = r[2]; bf[np * 2 + 1][1] = r[3];
            }
#pragma unroll
            for (int mi = 0; mi < 4; mi++)
#pragma unroll
                for (int ni = 0; ni < 4; ni++) hmma16(acc[mi][ni], af[mi], bf[ni]);
        }
    }

    // ---- epilogue ----
    const int mrow = (lane >> 2);
    const int ncol = (lane & 3) * 2;
    const float rscale = 0.11180339887498949f;  // 1/sqrt(80)

    int mat = 0;
    const float* bias = bq;
    if (MODE == 1) {
        mat = bn / 10;
        bias = (mat == 0) ? bq : (mat == 1) ? bk : bv;
    }
    const int nbase = (MODE == 1) ? (bn % 10) * 128 : bn * 128;

#pragma unroll
    for (int mi = 0; mi < 4; mi++) {
#pragma unroll
        for (int h2 = 0; h2 < 2; h2++) {
            int m = row0A + wm * 64 + mi * 16 + mrow + h2 * 8;
            if (m >= M) continue;
            int bb2 = m / S_, ss = m - bb2 * S_;
#pragma unroll
            for (int ni = 0; ni < 4; ni++) {
                int n0 = nbase + wn * 32 + ni * 8 + ncol;
                float vx = acc[mi][ni][h2 * 2] + bias[n0];
                float vy = acc[mi][ni][h2 * 2 + 1] + bias[n0 + 1];
                if (MODE == 0) {
                    float2 v = make_float2(vx, vy);
                    *(float2*)&Cf[(size_t)m * N_ + n0] = v;
                } else {
                    int h = n0 / HD_, d = n0 - h * HD_;
                    size_t idx = ((size_t)(bb2 * H_ + h) * S_ + ss) * HD_ + d;
                    if (mat == 0) {            // q: rope + scale
                        int j = d >> 1;
                        float c = fc[ss * HALF_ + j], sn = fs[ss * HALF_ + j];
                        float rx = (vx * c - vy * sn) * rscale;
                        float ry = (vx * sn + vy * c) * rscale;
                        __half2 hv = __floats2half2_rn(rx, ry);
                        *(__half2*)&q16[idx] = hv;
                    } else if (mat == 1) {     // k: rope
                        int j = d >> 1;
                        float c = fc[ss * HALF_ + j], sn = fs[ss * HALF_ + j];
                        float rx = vx * c - vy * sn;
                        float ry = vx * sn + vy * c;
                        __half2 hv = __floats2half2_rn(rx, ry);
                        *(__half2*)&k16[idx] = hv;
                    } else {                   // v
                        __half2 hv = __floats2half2_rn(vx, vy);
                        *(__half2*)&v16[idx] = hv;
                    }
                }
            }
        }
    }
}

// ---------------------------------------------------------------- fp16 HMMA flash attention (R14)
#define ASVB 176                  // 80 fp16 = 160B + 16B pad (col80=1.0, 81..87=0)
#define AQ_TILE (128*ASVB)        // 22528
#define AKV_TILE (64*ASVB)        // 11264
#define ATT_SMEM (AQ_TILE + 4*AKV_TILE)   // 67584

__global__ __launch_bounds__(256, 2)
void attn_hmma(const __half* __restrict__ q16,
               const __half* __restrict__ k16, const __half* __restrict__ v16,
               __half* __restrict__ at16)
{
    extern __shared__ __align__(16) char smem[];
    const uint32_t sb = smem_u32(smem);
    const uint32_t kv0 = sb + AQ_TILE;

    const int tid = threadIdx.x, wid = tid >> 5, lane = tid & 31;
    const int qt = blockIdx.x, h = blockIdx.y, b = blockIdx.z;
    const int bh = b * H_ + h;
    const size_t off = (size_t)bh * S_ * HD_;
    const int q0 = qt * 128;

#pragma unroll
    for (int t = 0; t < 5; t++) {
        int i = tid + t * 256;
        int rr = i / 10, seg = i % 10;
        int row = q0 + rr;
        int sz = (row < S_) ? 16 : 0;
        if (row >= S_) row = S_ - 1;
        const __half* sp = q16 + off + (size_t)row * HD_ + seg * 8;
        cp16(sb + rr * ASVB + seg * 16, sp, sz);
    }
    CP_COMMIT();

    auto load_kv = [&](int stage, int kt) {
#pragma unroll
        for (int t = 0; t < 5; t++) {
            int i = tid + t * 256;
            int tile = i / 640;
            int rr = (i % 640) / 10, seg = i % 10;
            int row = kt * 64 + rr;
            int sz = (row < S_) ? 16 : 0;
            if (row >= S_) row = S_ - 1;
            const __half* sp = (tile ? v16 : k16) + off + (size_t)row * HD_ + seg * 8;
            cp16(kv0 + (stage * 2 + tile) * AKV_TILE + rr * ASVB + seg * 16, sp, sz);
        }
        CP_COMMIT();
    };
    load_kv(0, 0);
    load_kv(1, 1);

    // V pad init: col 80 = 1.0 (ones column for row-sum), 81..87 = 0.
    if (tid < 128) {
        int stage = tid >> 6, row = tid & 63;
        __half* p = (__half*)(smem + AQ_TILE + (stage * 2 + 1) * AKV_TILE
                              + row * ASVB + 160);
        p[0] = __float2half(1.f);
#pragma unroll
        for (int z = 1; z < 8; z++) p[z] = __float2half(0.f);
    }

    CP_WAIT1();
    __syncthreads();

    const int r0 = lane >> 2, c0 = (lane & 3) * 2;
    float mreg[2] = {-1e30f, -1e30f};
    float out[11][4];
#pragma unroll
    for (int ni = 0; ni < 11; ni++)
#pragma unroll
        for (int c = 0; c < 4; c++) out[ni][c] = 0.f;

    for (int kt = 0; kt < 10; kt++) {
        const int cur = kt & 1;
        const uint32_t kbase = kv0 + cur * 2 * AKV_TILE;
        const uint32_t vbase0 = kbase + AKV_TILE;

        float sacc[8][4];
#pragma unroll
        for (int ni = 0; ni < 8; ni++)
#pragma unroll
            for (int c = 0; c < 4; c++) sacc[ni][c] = 0.f;

#pragma unroll
        for (int k16i = 0; k16i < 5; k16i++) {
            uint32_t qf[4], bf[8][2];
            uint32_t abase = sb + (wid * 16 + (lane & 15)) * ASVB
                           + (lane >> 4) * 16 + k16i * 32;
            ldx4(qf, abase);
#pragma unroll
            for (int nt = 0; nt < 4; nt++) {
                uint32_t r[4];
                uint32_t bb = kbase + (nt * 16 + ((lane >> 4) << 3) + (lane & 7)) * ASVB
                            + ((lane >> 3) & 1) * 16 + k16i * 32;
                ldx4(r, bb);
                bf[nt * 2][0] = r[0]; bf[nt * 2][1] = r[1];
                bf[nt * 2 + 1][0] = r[2]; bf[nt * 2 + 1][1] = r[3];
            }
#pragma unroll
            for (int ni = 0; ni < 8; ni++) hmma16(sacc[ni], qf, bf[ni]);
        }

        float mloc[2] = {-1e30f, -1e30f};
#pragma unroll
        for (int ni = 0; ni < 8; ni++)
#pragma unroll
            for (int h8 = 0; h8 < 2; h8++)
#pragma unroll
                for (int j = 0; j < 2; j++) {
                    int key = kt * 64 + ni * 8 + c0 + j;
                    float sv = (key < S_) ? sacc[ni][h8 * 2 + j] : -1e30f;
                    sacc[ni][h8 * 2 + j] = sv;
                    mloc[h8] = fmaxf(mloc[h8], sv);
                }
        float alpha[2];
#pragma unroll
        for (int h8 = 0; h8 < 2; h8++) {
            mloc[h8] = fmaxf(mloc[h8], __shfl_xor_sync(0xffffffffu, mloc[h8], 1));
            mloc[h8] = fmaxf(mloc[h8], __shfl_xor_sync(0xffffffffu, mloc[h8], 2));
            float mn = fmaxf(mloc[h8], mreg[h8]);
            alpha[h8] = __expf(mreg[h8] - mn);
            mreg[h8] = mn;
        }

        uint32_t pacc[8][2];
#pragma unroll
        for (int ni = 0; ni < 8; ni++)
#pragma unroll
            for (int h8 = 0; h8 < 2; h8++) {
                float e0 = __expf(sacc[ni][h8 * 2]     - mreg[h8]);
                float e1 = __expf(sacc[ni][h8 * 2 + 1] - mreg[h8]);
                __half2 th = __floats2half2_rn(e0, e1);
                pacc[ni][h8] = *(uint32_t*)&th;
            }

#pragma unroll
        for (int ni = 0; ni < 11; ni++)
#pragma unroll
            for (int h8 = 0; h8 < 2; h8++) {
                out[ni][h8 * 2]     *= alpha[h8];
                out[ni][h8 * 2 + 1] *= alpha[h8];
            }

#pragma unroll
        for (int kk = 0; kk < 4; kk++) {
            uint32_t pa[4] = { pacc[kk * 2][0], pacc[kk * 2][1],
                               pacc[kk * 2 + 1][0], pacc[kk * 2 + 1][1] };
            uint32_t vb = vbase0 + (kk * 16 + (lane & 15)) * ASVB + (lane >> 4) * 16;
#pragma unroll
            for (int nt = 0; nt < 5; nt++) {
                uint32_t rh[4];
                ldx4t(rh, vb + nt * 32);
                uint32_t vb0[2] = {rh[0], rh[1]}, vb1[2] = {rh[2], rh[3]};
                hmma16(out[nt * 2], pa, vb0);
                hmma16(out[nt * 2 + 1], pa, vb1);
            }
            {
                uint32_t rh[4];
                uint32_t vbo = vbase0 + (kk * 16 + (lane & 15)) * ASVB + 160;
                ldx4t(rh, vbo);
                uint32_t vb0[2] = {rh[0], rh[1]};
                hmma16(out[10], pa, vb0);
            }
        }

        __syncthreads();
        if (kt + 2 < 10) {
            load_kv(cur, kt + 2);
            CP_WAIT1();
        } else if (kt + 1 < 10) {
            CP_WAIT0();
        }
    }

#pragma unroll
    for (int h8 = 0; h8 < 2; h8++) {
        float l = __shfl_sync(0xffffffffu, out[10][h8 * 2], lane & ~3);
        int row = wid * 16 + r0 + h8 * 8;
        int srow = q0 + row;
        if (srow >= S_) continue;
        float rl = 1.f / l;
#pragma unroll
        for (int ni = 0; ni < 10; ni++) {
            int col = ni * 8 + c0;
            float vx = out[ni][h8 * 2] * rl;
            float vy = out[ni][h8 * 2 + 1] * rl;
            __half2 hv = __floats2half2_rn(vx, vy);
            size_t oidx = ((size_t)b * S_ + srow) * D_ + h * HD_ + col;
            *(__half2*)&at16[oidx] = hv;
        }
    }
}

// ----------------------------------------------------------------
extern "C" void kernel_launch(void* const* d_in, const int* in_sizes, int n_in,
                              void* d_out, int out_size)
{
    const float* hs = (const float*)d_in[0];
    const float* fc = (const float*)d_in[1];
    const float* fs = (const float*)d_in[2];
    const float* Wq = (const float*)d_in[3];
    const float* bq = (const float*)d_in[4];
    const float* Wk = (const float*)d_in[5];
    const float* bk = (const float*)d_in[6];
    const float* Wv = (const float*)d_in[7];
    const float* bv = (const float*)d_in[8];
    const float* Wo = (const float*)d_in[9];
    const float* bo = (const float*)d_in[10];
    float* out = (float*)d_out;

    __half *hs16, *w16, *at16, *q16, *k16, *v16;
    cudaGetSymbolAddress((void**)&hs16, g_hs16);
    cudaGetSymbolAddress((void**)&w16, g_w16);
    cudaGetSymbolAddress((void**)&at16, g_at16);
    cudaGetSymbolAddress((void**)&q16, g_q16);
    cudaGetSymbolAddress((void**)&k16, g_k16);
    cudaGetSymbolAddress((void**)&v16, g_v16);

    {
        int ntot = M_ * K_ + 4 * K_ * N_;
        conv_all<<<(ntot + 255) / 256, 256>>>(hs, Wq, Wk, Wv, Wo, hs16, w16);
    }

    cudaFuncSetAttribute(gemm_hmma<0>, cudaFuncAttributeMaxDynamicSharedMemorySize,
                         GEMM_SMEM);
    cudaFuncSetAttribute(gemm_hmma<1>, cudaFuncAttributeMaxDynamicSharedMemorySize,
                         GEMM_SMEM);
    size_t wsz = (size_t)K_ * N_;

    gemm_hmma<1><<<dim3(30, (M_ + 127) / 128), 256, GEMM_SMEM>>>(
        hs16, w16, bq, bk, bv,
        nullptr, q16, k16, v16, fc, fs, M_);

    cudaFuncSetAttribute(attn_hmma, cudaFuncAttributeMaxDynamicSharedMemorySize,
                         ATT_SMEM);
    attn_hmma<<<dim3(5, H_, B_), 256, ATT_SMEM>>>(q16, k16, v16, at16);

    gemm_hmma<0><<<dim3(10, (M_ + 127) / 128), 256, GEMM_SMEM>>>(
        at16, w16 + 3 * wsz, bo, bo, bo,
        out, nullptr, nullptr, nullptr, fc, fs, M_);
}

// round 17
// speedup vs baseline: 1.1284x; 1.0210x over previous
#include <cuda_runtime.h>
#include <cuda_bf16.h>
#include <cuda_fp16.h>
#include <math.h>
#include <stdint.h>

#define B_    16
#define S_    577
#define D_    1280
#define H_    16
#define HD_   80
#define HALF_ 40
#define M_    (B_*S_)   // 9232
#define K_    1280
#define N_    1280

// ---------------------------------------------------------------- scratch
__device__ __align__(16) __half g_hs16[M_*K_];
__device__ __align__(16) __half g_w16[4*K_*N_];
__device__ __align__(16) __half g_at16[M_*K_];
__device__ __align__(16) __half g_q16[B_*H_*S_*HD_];
__device__ __align__(16) __half g_k16[B_*H_*S_*HD_];
__device__ __align__(16) __half g_v16[B_*H_*S_*HD_];

// ---------------------------------------------------------------- helpers
__device__ __forceinline__ uint32_t smem_u32(const void* p) {
    uint32_t a;
    asm("{ .reg .u64 t; cvta.to.shared.u64 t, %1; cvt.u32.u64 %0, t; }"
        : "=r"(a) : "l"(p));
    return a;
}
__device__ __forceinline__ void cp16(uint32_t dst, const void* src, int sz) {
    asm volatile("cp.async.cg.shared.global [%0], [%1], 16, %2;"
                 :: "r"(dst), "l"(src), "r"(sz) : "memory");
}
#define CP_COMMIT() asm volatile("cp.async.commit_group;" ::: "memory")
#define CP_WAIT0()  asm volatile("cp.async.wait_group 0;" ::: "memory")
#define CP_WAIT1()  asm volatile("cp.async.wait_group 1;" ::: "memory")

__device__ __forceinline__ void ldx4(uint32_t* r, uint32_t addr) {
    asm volatile("ldmatrix.sync.aligned.m8n8.x4.shared.b16 {%0,%1,%2,%3}, [%4];"
                 : "=r"(r[0]), "=r"(r[1]), "=r"(r[2]), "=r"(r[3]) : "r"(addr));
}
__device__ __forceinline__ void ldx4t(uint32_t* r, uint32_t addr) {
    asm volatile("ldmatrix.sync.aligned.m8n8.x4.trans.shared.b16 {%0,%1,%2,%3}, [%4];"
                 : "=r"(r[0]), "=r"(r[1]), "=r"(r[2]), "=r"(r[3]) : "r"(addr));
}
__device__ __forceinline__ void hmma16(float* d, const uint32_t* a, const uint32_t* b) {
    asm volatile(
        "mma.sync.aligned.m16n8k16.row.col.f32.f16.f16.f32 "
        "{%0,%1,%2,%3}, {%4,%5,%6,%7}, {%8,%9}, {%0,%1,%2,%3};"
        : "+f"(d[0]), "+f"(d[1]), "+f"(d[2]), "+f"(d[3])
        : "r"(a[0]), "r"(a[1]), "r"(a[2]), "r"(a[3]), "r"(b[0]), "r"(b[1]));
}

// ---------------------------------------------------------------- merged fp32 -> fp16 converts
__global__ __launch_bounds__(256)
void conv_all(const float* __restrict__ hs,
              const float* __restrict__ w0, const float* __restrict__ w1,
              const float* __restrict__ w2, const float* __restrict__ w3,
              __half* __restrict__ hs16, __half* __restrict__ w16)
{
    const int n1 = M_ * K_;
    const int nw = K_ * N_;
    int i = blockIdx.x * blockDim.x + threadIdx.x;
    if (i < n1) {
        hs16[i] = __float2half_rn(hs[i]);
    } else {
        int k = i - n1;
        if (k >= 4 * nw) return;
        int mat = k / nw, off = k - mat * nw;
        const float* src = (mat == 0) ? w0 : (mat == 1) ? w1 : (mat == 2) ? w2 : w3;
        w16[k] = __float2half_rn(src[off]);
    }
}

// ---------------------------------------------------------------- fp16 HMMA GEMM
// CTA tile 128x128, BK=64; 8 warps as 2(M) x 4(N), warp tile 64x32.
// 3-stage cp.async pipeline; loads for stage it+2 issued AFTER sync(it),
// so one __syncthreads per 64-wide k-iteration (20 barriers total).
#define SPADB 144                 // 128 B data + 16 pad (bank step 36%32=4: conflict-free)
#define TILEB (128*SPADB)         // 18432
#define STAGEB (2*TILEB)          // 36864
#define GEMM_SMEM (3*STAGEB)      // 110592
#define NIT (K_/64)               // 20

template<int MODE>
__global__ __launch_bounds__(256, 2)
void gemm_hmma(const __half* __restrict__ Ah, const __half* __restrict__ Bh,
               const float* __restrict__ bq, const float* __restrict__ bk,
               const float* __restrict__ bv,
               float* __restrict__ Cf,
               __half* __restrict__ q16, __half* __restrict__ k16,
               __half* __restrict__ v16,
               const float* __restrict__ fc, const float* __restrict__ fs,
               int M)
{
    extern __shared__ __align__(16) char smem[];
    const int tid = threadIdx.x, wid = tid >> 5, lane = tid & 31;
    const int bn = blockIdx.x, bm = blockIdx.y;
    const int wm = wid >> 2, wn = wid & 3;
    const int row0A = bm * 128, row0B = bn * 128;
    const uint32_t sbase = smem_u32(smem);

    float acc[4][4][4];
#pragma unroll
    for (int i = 0; i < 4; i++)
#pragma unroll
        for (int j = 0; j < 4; j++)
#pragma unroll
            for (int c = 0; c < 4; c++) acc[i][j][c] = 0.f;

    // stage = 2048 cp16 units = 8 per thread
    auto load_stage = [&](int st, int k0) {
        uint32_t sdst = sbase + st * STAGEB;
#pragma unroll
        for (int t = 0; t < 8; t++) {
            int idx = tid + t * 256;          // 0..2047
            int tile = idx >> 10;             // 0=A,1=B
            int w = idx & 1023;
            int r = w >> 3, seg = w & 7;      // 128 rows x 8 segs (16B)
            uint32_t d = sdst + tile * TILEB + r * SPADB + seg * 16;
            const __half* sp;
            int sz = 16;
            if (tile == 0) {
                int row = row0A + r;
                if (row >= M) { row = M - 1; sz = 0; }
                sp = Ah + (size_t)row * K_ + k0 + seg * 8;
            } else {
                int row = row0B + r;
                sp = Bh + (size_t)row * K_ + k0 + seg * 8;
            }
            cp16(d, sp, sz);
        }
        CP_COMMIT();
    };

    const uint32_t a_lane = (uint32_t)((wm * 64 + (lane & 15)) * SPADB + (lane >> 4) * 16);
    const uint32_t b_lane = (uint32_t)((wn * 32 + ((lane >> 4) << 3) + (lane & 7)) * SPADB
                                       + ((lane >> 3) & 1) * 16);

    load_stage(0, 0);
    load_stage(1, 64);

    int stq = 2;   // next stage slot to fill (mod 3)
    for (int it = 0; it < NIT; it++) {
        if (it + 1 < NIT) { CP_WAIT1(); }
        else              { CP_WAIT0(); }
        __syncthreads();   // single barrier per iteration
        if (it + 2 < NIT) {
            load_stage(stq, (it + 2) * 64);
            stq = (stq == 2) ? 0 : stq + 1;
        }

        uint32_t scur = sbase + (it % 3) * STAGEB;
#pragma unroll
        for (int kk = 0; kk < 4; kk++) {
            uint32_t ab = scur + a_lane + kk * 32;
            uint32_t bb = scur + TILEB + b_lane + kk * 32;

            uint32_t af[4][4], bf[4][2];
#pragma unroll
            for (int mi = 0; mi < 4; mi++) ldx4(af[mi], ab + mi * 16 * SPADB);
#pragma unroll
            for (int np = 0; np < 2; np++) {
                uint32_t r[4];
                ldx4(r, bb + np * 16 * SPADB);
                bf[np * 2][0] = r[0]; bf[np * 2][1] = r[1];
                bf[np * 2 + 1][0] = r[2]; bf[np * 2 + 1][1] = r[3];
            }
#pragma unroll
            for (int mi = 0; mi < 4; mi++)
#pragma unroll
                for (int ni = 0; ni < 4; ni++) hmma16(acc[mi][ni], af[mi], bf[ni]);
        }
    }

    // ---- epilogue ----
    const int mrow = (lane >> 2);
    const int ncol = (lane & 3) * 2;
    const float rscale = 0.11180339887498949f;  // 1/sqrt(80)

    int mat = 0;
    const float* bias = bq;
    if (MODE == 1) {
        mat = bn / 10;
        bias = (mat == 0) ? bq : (mat == 1) ? bk : bv;
    }
    const int nbase = (MODE == 1) ? (bn % 10) * 128 : bn * 128;

#pragma unroll
    for (int mi = 0; mi < 4; mi++) {
#pragma unroll
        for (int h2 = 0; h2 < 2; h2++) {
            int m = row0A + wm * 64 + mi * 16 + mrow + h2 * 8;
            if (m >= M) continue;
            int bb2 = m / S_, ss = m - bb2 * S_;
#pragma unroll
            for (int ni = 0; ni < 4; ni++) {
                int n0 = nbase + wn * 32 + ni * 8 + ncol;
                float vx = acc[mi][ni][h2 * 2] + bias[n0];
                float vy = acc[mi][ni][h2 * 2 + 1] + bias[n0 + 1];
                if (MODE == 0) {
                    float2 v = make_float2(vx, vy);
                    *(float2*)&Cf[(size_t)m * N_ + n0] = v;
                } else {
                    int h = n0 / HD_, d = n0 - h * HD_;
                    size_t idx = ((size_t)(bb2 * H_ + h) * S_ + ss) * HD_ + d;
                    if (mat == 0) {            // q: rope + scale
                        int j = d >> 1;
                        float c = fc[ss * HALF_ + j], sn = fs[ss * HALF_ + j];
                        float rx = (vx * c - vy * sn) * rscale;
                        float ry = (vx * sn + vy * c) * rscale;
                        __half2 hv = __floats2half2_rn(rx, ry);
                        *(__half2*)&q16[idx] = hv;
                    } else if (mat == 1) {     // k: rope
                        int j = d >> 1;
                        float c = fc[ss * HALF_ + j], sn = fs[ss * HALF_ + j];
                        float rx = vx * c - vy * sn;
                        float ry = vx * sn + vy * c;
                        __half2 hv = __floats2half2_rn(rx, ry);
                        *(__half2*)&k16[idx] = hv;
                    } else {                   // v
                        __half2 hv = __floats2half2_rn(vx, vy);
                        *(__half2*)&v16[idx] = hv;
                    }
                }
            }
        }
    }
}

// ---------------------------------------------------------------- fp16 HMMA flash attention (R14/R16)
#define ASVB 176                  // 80 fp16 = 160B + 16B pad (col80=1.0, 81..87=0)
#define AQ_TILE (128*ASVB)        // 22528
#define AKV_TILE (64*ASVB)        // 11264
#define ATT_SMEM (AQ_TILE + 4*AKV_TILE)   // 67584

__global__ __launch_bounds__(256, 2)
void attn_hmma(const __half* __restrict__ q16,
               const __half* __restrict__ k16, const __half* __restrict__ v16,
               __half* __restrict__ at16)
{
    extern __shared__ __align__(16) char smem[];
    const uint32_t sb = smem_u32(smem);
    const uint32_t kv0 = sb + AQ_TILE;

    const int tid = threadIdx.x, wid = tid >> 5, lane = tid & 31;
    const int qt = blockIdx.x, h = blockIdx.y, b = blockIdx.z;
    const int bh = b * H_ + h;
    const size_t off = (size_t)bh * S_ * HD_;
    const int q0 = qt * 128;

#pragma unroll
    for (int t = 0; t < 5; t++) {
        int i = tid + t * 256;
        int rr = i / 10, seg = i % 10;
        int row = q0 + rr;
        int sz = (row < S_) ? 16 : 0;
        if (row >= S_) row = S_ - 1;
        const __half* sp = q16 + off + (size_t)row * HD_ + seg * 8;
        cp16(sb + rr * ASVB + seg * 16, sp, sz);
    }
    CP_COMMIT();

    auto load_kv = [&](int stage, int kt) {
#pragma unroll
        for (int t = 0; t < 5; t++) {
            int i = tid + t * 256;
            int tile = i / 640;
            int rr = (i % 640) / 10, seg = i % 10;
            int row = kt * 64 + rr;
            int sz = (row < S_) ? 16 : 0;
            if (row >= S_) row = S_ - 1;
            const __half* sp = (tile ? v16 : k16) + off + (size_t)row * HD_ + seg * 8;
            cp16(kv0 + (stage * 2 + tile) * AKV_TILE + rr * ASVB + seg * 16, sp, sz);
        }
        CP_COMMIT();
    };
    load_kv(0, 0);
    load_kv(1, 1);

    // V pad init: col 80 = 1.0 (ones column for row-sum), 81..87 = 0.
    if (tid < 128) {
        int stage = tid >> 6, row = tid & 63;
        __half* p = (__half*)(smem + AQ_TILE + (stage * 2 + 1) * AKV_TILE
                              + row * ASVB + 160);
        p[0] = __float2half(1.f);
#pragma unroll
        for (int z = 1; z < 8; z++) p[z] = __float2half(0.f);
    }

    CP_WAIT1();
    __syncthreads();

    const int r0 = lane >> 2, c0 = (lane & 3) * 2;
    float mreg[2] = {-1e30f, -1e30f};
    float out[11][4];
#pragma unroll
    for (int ni = 0; ni < 11; ni++)
#pragma unroll
        for (int c = 0; c < 4; c++) out[ni][c] = 0.f;

    for (int kt = 0; kt < 10; kt++) {
        const int cur = kt & 1;
        const uint32_t kbase = kv0 + cur * 2 * AKV_TILE;
        const uint32_t vbase0 = kbase + AKV_TILE;

        float sacc[8][4];
#pragma unroll
        for (int ni = 0; ni < 8; ni++)
#pragma unroll
            for (int c = 0; c < 4; c++) sacc[ni][c] = 0.f;

#pragma unroll
        for (int k16i = 0; k16i < 5; k16i++) {
            uint32_t qf[4], bf[8][2];
            uint32_t abase = sb + (wid * 16 + (lane & 15)) * ASVB
                           + (lane >> 4) * 16 + k16i * 32;
            ldx4(qf, abase);
#pragma unroll
            for (int nt = 0; nt < 4; nt++) {
                uint32_t r[4];
                uint32_t bb = kbase + (nt * 16 + ((lane >> 4) << 3) + (lane & 7)) * ASVB
                            + ((lane >> 3) & 1) * 16 + k16i * 32;
                ldx4(r, bb);
                bf[nt * 2][0] = r[0]; bf[nt * 2][1] = r[1];
                bf[nt * 2 + 1][0] = r[2]; bf[nt * 2 + 1][1] = r[3];
            }
#pragma unroll
            for (int ni = 0; ni < 8; ni++) hmma16(sacc[ni], qf, bf[ni]);
        }

        float mloc[2] = {-1e30f, -1e30f};
#pragma unroll
        for (int ni = 0; ni < 8; ni++)
#pragma unroll
            for (int h8 = 0; h8 < 2; h8++)
#pragma unroll
                for (int j = 0; j < 2; j++) {
                    int key = kt * 64 + ni * 8 + c0 + j;
                    float sv = (key < S_) ? sacc[ni][h8 * 2 + j] : -1e30f;
                    sacc[ni][h8 * 2 + j] = sv;
                    mloc[h8] = fmaxf(mloc[h8], sv);
                }
        float alpha[2];
#pragma unroll
        for (int h8 = 0; h8 < 2; h8++) {
            mloc[h8] = fmaxf(mloc[h8], __shfl_xor_sync(0xffffffffu, mloc[h8], 1));
            mloc[h8] = fmaxf(mloc[h8], __shfl_xor_sync(0xffffffffu, mloc[h8], 2));
            float mn = fmaxf(mloc[h8], mreg[h8]);
            alpha[h8] = __expf(mreg[h8] - mn);
            mreg[h8] = mn;
        }

        uint32_t pacc[8][2];
#pragma unroll
        for (int ni = 0; ni < 8; ni++)
#pragma unroll
            for (int h8 = 0; h8 < 2; h8++) {
                float e0 = __expf(sacc[ni][h8 * 2]     - mreg[h8]);
                float e1 = __expf(sacc[ni][h8 * 2 + 1] - mreg[h8]);
                __half2 th = __floats2half2_rn(e0, e1);
                pacc[ni][h8] = *(uint32_t*)&th;
            }

#pragma unroll
        for (int ni = 0; ni < 11; ni++)
#pragma unroll
            for (int h8 = 0; h8 < 2; h8++) {
                out[ni][h8 * 2]     *= alpha[h8];
                out[ni][h8 * 2 + 1] *= alpha[h8];
            }

#pragma unroll
        for (int kk = 0; kk < 4; kk++) {
            uint32_t pa[4] = { pacc[kk * 2][0], pacc[kk * 2][1],
                               pacc[kk * 2 + 1][0], pacc[kk * 2 + 1][1] };
            uint32_t vb = vbase0 + (kk * 16 + (lane & 15)) * ASVB + (lane >> 4) * 16;
#pragma unroll
            for (int nt = 0; nt < 5; nt++) {
                uint32_t rh[4];
                ldx4t(rh, vb + nt * 32);
                uint32_t vb0[2] = {rh[0], rh[1]}, vb1[2] = {rh[2], rh[3]};
                hmma16(out[nt * 2], pa, vb0);
                hmma16(out[nt * 2 + 1], pa, vb1);
            }
            {
                uint32_t rh[4];
                uint32_t vbo = vbase0 + (kk * 16 + (lane & 15)) * ASVB + 160;
                ldx4t(rh, vbo);
                uint32_t vb0[2] = {rh[0], rh[1]};
                hmma16(out[10], pa, vb0);
            }
        }

        __syncthreads();
        if (kt + 2 < 10) {
            load_kv(cur, kt + 2);
            CP_WAIT1();
        } else if (kt + 1 < 10) {
            CP_WAIT0();
        }
    }

#pragma unroll
    for (int h8 = 0; h8 < 2; h8++) {
        float l = __shfl_sync(0xffffffffu, out[10][h8 * 2], lane & ~3);
        int row = wid * 16 + r0 + h8 * 8;
        int srow = q0 + row;
        if (srow >= S_) continue;
        float rl = 1.f / l;
#pragma unroll
        for (int ni = 0; ni < 10; ni++) {
            int col = ni * 8 + c0;
            float vx = out[ni][h8 * 2] * rl;
            float vy = out[ni][h8 * 2 + 1] * rl;
            __half2 hv = __floats2half2_rn(vx, vy);
            size_t oidx = ((size_t)b * S_ + srow) * D_ + h * HD_ + col;
            *(__half2*)&at16[oidx] = hv;
        }
    }
}

// ----------------------------------------------------------------
extern "C" void kernel_launch(void* const* d_in, const int* in_sizes, int n_in,
                              void* d_out, int out_size)
{
    const float* hs = (const float*)d_in[0];
    const float* fc = (const float*)d_in[1];
    const float* fs = (const float*)d_in[2];
    const float* Wq = (const float*)d_in[3];
    const float* bq = (const float*)d_in[4];
    const float* Wk = (const float*)d_in[5];
    const float* bk = (const float*)d_in[6];
    const float* Wv = (const float*)d_in[7];
    const float* bv = (const float*)d_in[8];
    const float* Wo = (const float*)d_in[9];
    const float* bo = (const float*)d_in[10];
    float* out = (float*)d_out;

    __half *hs16, *w16, *at16, *q16, *k16, *v16;
    cudaGetSymbolAddress((void**)&hs16, g_hs16);
    cudaGetSymbolAddress((void**)&w16, g_w16);
    cudaGetSymbolAddress((void**)&at16, g_at16);
    cudaGetSymbolAddress((void**)&q16, g_q16);
    cudaGetSymbolAddress((void**)&k16, g_k16);
    cudaGetSymbolAddress((void**)&v16, g_v16);

    {
        int ntot = M_ * K_ + 4 * K_ * N_;
        conv_all<<<(ntot + 255) / 256, 256>>>(hs, Wq, Wk, Wv, Wo, hs16, w16);
    }

    cudaFuncSetAttribute(gemm_hmma<0>, cudaFuncAttributeMaxDynamicSharedMemorySize,
                         GEMM_SMEM);
    cudaFuncSetAttribute(gemm_hmma<1>, cudaFuncAttributeMaxDynamicSharedMemorySize,
                         GEMM_SMEM);
    size_t wsz = (size_t)K_ * N_;

    gemm_hmma<1><<<dim3(30, (M_ + 127) / 128), 256, GEMM_SMEM>>>(
        hs16, w16, bq, bk, bv,
        nullptr, q16, k16, v16, fc, fs, M_);

    cudaFuncSetAttribute(attn_hmma, cudaFuncAttributeMaxDynamicSharedMemorySize,
                         ATT_SMEM);
    attn_hmma<<<dim3(5, H_, B_), 256, ATT_SMEM>>>(q16, k16, v16, at16);

    gemm_hmma<0><<<dim3(10, (M_ + 127) / 128), 256, GEMM_SMEM>>>(
        at16, w16 + 3 * wsz, bo, bo, bo,
        out, nullptr, nullptr, nullptr, fc, fs, M_);
}